// round 6
// baseline (speedup 1.0000x reference)
#include <cuda_runtime.h>
#include <cuda_fp16.h>
#include <math.h>
#include <stdint.h>

// ---------------------------------------------------------------------------
// Problem constants
// ---------------------------------------------------------------------------
#define D_IN   64
#define HID    256
#define NPAR   800
#define BMAX   131072
#define MINW   0.001f
#define MIND   0.001f
#define EPSC   1e-12f

// Prepared weights (fp16 hi/lo splits, transposed to [n][k]) + P scratch
__device__ __half g_W1h[HID * 32],  g_W1l[HID * 32];
__device__ __half g_W2h[NPAR * HID], g_W2l[NPAR * HID];
__device__ float  g_P[(size_t)BMAX * NPAR];          // 419 MB

// ---------------------------------------------------------------------------
// smem layout for kgemm (bytes)
// ---------------------------------------------------------------------------
#define OFF_AH   0                    // A (H) hi : 128 rows x 512B (swizzled)
#define OFF_AL   65536                // A lo
#define OFF_U    131072               // union, 51200 B
//   phase1: XH@U+0 (8192), XL@U+8192, W1H@U+16384, W1L@U+32768
//   phase2: W2BUF0@U+0 (hi 12800 + lo 12800), W2BUF1@U+25600
#define OFF_B1   182272               // 256 f
#define SMEM_TOT 183296

// ---------------------------------------------------------------------------
// helpers
// ---------------------------------------------------------------------------
__device__ __forceinline__ uint32_t smem_u32(const void* p) {
    uint32_t a;
    asm("{ .reg .u64 t; cvta.to.shared.u64 t, %1; cvt.u32.u64 %0, t; }" : "=r"(a) : "l"(p));
    return a;
}
__device__ __forceinline__ void ldsm4(uint32_t r[4], uint32_t addr) {
    asm volatile("ldmatrix.sync.aligned.m8n8.x4.shared.b16 {%0,%1,%2,%3}, [%4];"
                 : "=r"(r[0]), "=r"(r[1]), "=r"(r[2]), "=r"(r[3]) : "r"(addr));
}
__device__ __forceinline__ void mma16816(float c[4], const uint32_t a[4], const uint32_t b[2]) {
    asm volatile("mma.sync.aligned.m16n8k16.row.col.f32.f16.f16.f32 "
                 "{%0,%1,%2,%3}, {%4,%5,%6,%7}, {%8,%9}, {%0,%1,%2,%3};"
                 : "+f"(c[0]), "+f"(c[1]), "+f"(c[2]), "+f"(c[3])
                 : "r"(a[0]), "r"(a[1]), "r"(a[2]), "r"(a[3]), "r"(b[0]), "r"(b[1]));
}
__device__ __forceinline__ uint32_t packh2(float v0, float v1) {
    __half h0 = __float2half_rn(v0), h1 = __float2half_rn(v1);
    return (uint32_t)__half_as_ushort(h0) | ((uint32_t)__half_as_ushort(h1) << 16);
}

// A region (512B rows): byte = r*512 + ((g ^ (r&7))<<4); g = 16B group 0..31
__device__ __forceinline__ uint32_t aoff(int r, int g) {
    return (uint32_t)(r * 512 + ((g ^ (r & 7)) << 4));
}
// 64B-row regions (X, W1t, W2 k32 chunks): byte = n*64 + ((g ^ ((n>>1)&3))<<4)
__device__ __forceinline__ uint32_t boff(int n, int g) {
    return (uint32_t)(n * 64 + ((g ^ ((n >> 1) & 3)) << 4));
}

// ---------------------------------------------------------------------------
// prep: transpose + fp16-split W1, W2
// ---------------------------------------------------------------------------
__global__ void kprep(const float* __restrict__ W1, const float* __restrict__ W2) {
    int n = blockIdx.x, k = threadIdx.x;
    if (n < NPAR) {
        float v = W2[(size_t)k * NPAR + n];
        __half h = __float2half_rn(v);
        g_W2h[n * HID + k] = h;
        g_W2l[n * HID + k] = __float2half_rn(v - __half2float(h));
    } else {
        int nn = n - NPAR;
        if (k < 32) {
            float v = W1[k * HID + nn];
            __half h = __float2half_rn(v);
            g_W1h[nn * 32 + k] = h;
            g_W1l[nn * 32 + k] = __float2half_rn(v - __half2float(h));
        }
    }
}

// ---------------------------------------------------------------------------
// kgemm: H = relu(X@W1+b1) in smem, then P = H @ W2 -> g_P. 512 thr, 128 rows.
// No epilogue, no spline — pure tensor throughput.
// ---------------------------------------------------------------------------
__global__ __launch_bounds__(512, 1)
void kgemm(const float* __restrict__ X,
           const float* __restrict__ b1, int B)
{
    extern __shared__ char sm[];
    const uint32_t sb = smem_u32(sm);
    const int tid = threadIdx.x, lane = tid & 31, wid = tid >> 5;
    const int wm = wid >> 2, wn = wid & 3;
    const int rbase = blockIdx.x * 128;

    float* b1s = (float*)(sm + OFF_B1);
    if (tid < 256) b1s[tid] = b1[tid];

    // ---- phase-1 operand staging: X split + W1t ----
    {
        int r = tid >> 2, q = tid & 3;
        const float* xp = X + (size_t)(rbase + r) * D_IN + q * 8;
        float4 v0 = *(const float4*)xp, v1 = *(const float4*)(xp + 4);
        float vv[8] = {v0.x, v0.y, v0.z, v0.w, v1.x, v1.y, v1.z, v1.w};
        ushort hh[8], hl[8];
#pragma unroll
        for (int j = 0; j < 8; j++) {
            __half h = __float2half_rn(vv[j]);
            hh[j] = __half_as_ushort(h);
            hl[j] = __half_as_ushort(__float2half_rn(vv[j] - __half2float(h)));
        }
        uint32_t off = boff(r, q);
        *(uint4*)(sm + OFF_U + off)        = *(uint4*)hh;   // XH
        *(uint4*)(sm + OFF_U + 8192 + off) = *(uint4*)hl;   // XL
    }
#pragma unroll
    for (int s = 0; s < 4; s++) {
        int i = tid + s * 512;          // 2048 = 2 splits x 256 rows x 4 groups
        int split = i >> 10, ii = i & 1023;
        int n = ii >> 2, g = ii & 3;
        const __half* src = split ? g_W1l : g_W1h;
        uint4 v = *(const uint4*)(src + n * 32 + g * 8);
        *(uint4*)(sm + OFF_U + 16384 + split * 16384 + boff(n, g)) = v;
    }
    __syncthreads();

    // ---- phase-1 mma: H = relu(X @ W1 + b1), warp tile m32 x n64 ----
    float acc1[2][8][4];
#pragma unroll
    for (int i = 0; i < 2; i++)
#pragma unroll
        for (int j = 0; j < 8; j++)
#pragma unroll
            for (int c = 0; c < 4; c++) acc1[i][j][c] = 0.f;

#pragma unroll
    for (int t = 0; t < 2; t++) {
        uint32_t aH[2][4], aL[2][4], bb[8][2];
#pragma unroll
        for (int i = 0; i < 2; i++) {
            int r = wm * 32 + i * 16 + (lane & 15);
            int g = 2 * t + (lane >> 4);
            ldsm4(aH[i], sb + OFF_U + boff(r, g));          // XH
            ldsm4(aL[i], sb + OFF_U + 8192 + boff(r, g));   // XL
        }
#pragma unroll
        for (int p = 0; p < 4; p++) {
            int jj = wn * 8 + ((lane < 16) ? 2 * p : 2 * p + 1);
            int n = jj * 8 + (lane & 7);
            int g = 2 * t + ((lane >> 3) & 1);
            uint32_t r4[4];
            ldsm4(r4, sb + OFF_U + 16384 + boff(n, g));     // W1H
            bb[2 * p][0] = r4[0]; bb[2 * p][1] = r4[1];
            bb[2 * p + 1][0] = r4[2]; bb[2 * p + 1][1] = r4[3];
        }
#pragma unroll
        for (int i = 0; i < 2; i++)
#pragma unroll
            for (int j = 0; j < 8; j++) {
                mma16816(acc1[i][j], aH[i], bb[j]);
                mma16816(acc1[i][j], aL[i], bb[j]);
            }
#pragma unroll
        for (int p = 0; p < 4; p++) {
            int jj = wn * 8 + ((lane < 16) ? 2 * p : 2 * p + 1);
            int n = jj * 8 + (lane & 7);
            int g = 2 * t + ((lane >> 3) & 1);
            uint32_t r4[4];
            ldsm4(r4, sb + OFF_U + 32768 + boff(n, g));     // W1L
            bb[2 * p][0] = r4[0]; bb[2 * p][1] = r4[1];
            bb[2 * p + 1][0] = r4[2]; bb[2 * p + 1][1] = r4[3];
        }
#pragma unroll
        for (int i = 0; i < 2; i++)
#pragma unroll
            for (int j = 0; j < 8; j++)
                mma16816(acc1[i][j], aH[i], bb[j]);
    }

    // ---- phase-1 epilogue: +b1, relu, fp16-split into A region ----
#pragma unroll
    for (int i = 0; i < 2; i++)
#pragma unroll
        for (int j = 0; j < 8; j++) {
            int col = wn * 64 + j * 8 + 2 * (lane & 3);
            float bv0 = b1s[col], bv1 = b1s[col + 1];
            int r0 = wm * 32 + i * 16 + (lane >> 2);
#pragma unroll
            for (int half = 0; half < 2; half++) {
                int r = r0 + half * 8;
                float v0 = fmaxf(acc1[i][j][2 * half] + bv0, 0.f);
                float v1 = fmaxf(acc1[i][j][2 * half + 1] + bv1, 0.f);
                __half h0 = __float2half_rn(v0), h1 = __float2half_rn(v1);
                uint32_t hi = (uint32_t)__half_as_ushort(h0) |
                              ((uint32_t)__half_as_ushort(h1) << 16);
                uint32_t lo = packh2(v0 - __half2float(h0), v1 - __half2float(h1));
                uint32_t off = aoff(r, col >> 3) + (col & 7) * 2;
                *(uint32_t*)(sm + OFF_AH + off) = hi;
                *(uint32_t*)(sm + OFF_AL + off) = lo;
            }
        }
    __syncthreads();

    // ---- phase-2: P = H @ W2 per 200-col N-tile (4 tiles), STG to g_P ----
    for (int nt = 0; nt < 4; nt++) {
        const int nbase = nt * 200;
        float acc[2][7][4];
#pragma unroll
        for (int i = 0; i < 2; i++)
#pragma unroll
            for (int t = 0; t < 7; t++)
#pragma unroll
                for (int c = 0; c < 4; c++) acc[i][t][c] = 0.f;

        // load chunk 0 into buf 0 (k32: hi 12800 + lo 12800)
#pragma unroll
        for (int s = 0; s < 4; s++) {
            int i = tid + s * 512;
            if (i < 1600) {
                int split = i >= 800, ii = i - split * 800;
                int n = ii >> 2, g = ii & 3;
                const __half* src = split ? g_W2l : g_W2h;
                uint4 v = *(const uint4*)(src + (size_t)(nbase + n) * HID + g * 8);
                *(uint4*)(sm + OFF_U + split * 12800 + boff(n, g)) = v;
            }
        }
        __syncthreads();

        for (int kc = 0; kc < 8; kc++) {
            const uint32_t bufhi = OFF_U + (kc & 1) * 25600;
            const uint32_t buflo = bufhi + 12800;

            // LDG-prefetch next chunk
            uint4 pf[4];
            if (kc < 7) {
#pragma unroll
                for (int s = 0; s < 4; s++) {
                    int i = tid + s * 512;
                    if (i < 1600) {
                        int split = i >= 800, ii = i - split * 800;
                        int n = ii >> 2, g = ii & 3;
                        const __half* src = split ? g_W2l : g_W2h;
                        pf[s] = *(const uint4*)(src + (size_t)(nbase + n) * HID +
                                                (kc + 1) * 32 + g * 8);
                    }
                }
            }

#pragma unroll
            for (int tt = 0; tt < 2; tt++) {
                const int tg = kc * 2 + tt;
                uint32_t aH[2][4], aL[2][4], bb[7][2];
#pragma unroll
                for (int i = 0; i < 2; i++) {
                    int r = wm * 32 + i * 16 + (lane & 15);
                    int g = 2 * tg + (lane >> 4);
                    ldsm4(aH[i], sb + OFF_AH + aoff(r, g));
                }
#pragma unroll
                for (int p = 0; p < 4; p++) {
                    int ta = 2 * p, tb2 = (2 * p + 1 < 7) ? 2 * p + 1 : 6;
                    int t = (lane < 16) ? ta : tb2;
                    int j = wn + 4 * t; if (j > 24) j = 24;
                    int n = j * 8 + (lane & 7);
                    int g = 2 * tt + ((lane >> 3) & 1);
                    uint32_t r4[4];
                    ldsm4(r4, sb + bufhi + boff(n, g));
                    bb[ta][0] = r4[0]; bb[ta][1] = r4[1];
                    if (2 * p + 1 < 7) { bb[2 * p + 1][0] = r4[2]; bb[2 * p + 1][1] = r4[3]; }
                }
#pragma unroll
                for (int t = 0; t < 7; t++)
                    if (t < 6 || wn == 0) {
                        mma16816(acc[0][t], aH[0], bb[t]);
                        mma16816(acc[1][t], aH[1], bb[t]);
                    }
#pragma unroll
                for (int i = 0; i < 2; i++) {
                    int r = wm * 32 + i * 16 + (lane & 15);
                    int g = 2 * tg + (lane >> 4);
                    ldsm4(aL[i], sb + OFF_AL + aoff(r, g));
                }
#pragma unroll
                for (int t = 0; t < 7; t++)
                    if (t < 6 || wn == 0) {
                        mma16816(acc[0][t], aL[0], bb[t]);
                        mma16816(acc[1][t], aL[1], bb[t]);
                    }
#pragma unroll
                for (int p = 0; p < 4; p++) {
                    int ta = 2 * p, tb2 = (2 * p + 1 < 7) ? 2 * p + 1 : 6;
                    int t = (lane < 16) ? ta : tb2;
                    int j = wn + 4 * t; if (j > 24) j = 24;
                    int n = j * 8 + (lane & 7);
                    int g = 2 * tt + ((lane >> 3) & 1);
                    uint32_t r4[4];
                    ldsm4(r4, sb + buflo + boff(n, g));
                    bb[ta][0] = r4[0]; bb[ta][1] = r4[1];
                    if (2 * p + 1 < 7) { bb[2 * p + 1][0] = r4[2]; bb[2 * p + 1][1] = r4[3]; }
                }
#pragma unroll
                for (int t = 0; t < 7; t++)
                    if (t < 6 || wn == 0) {
                        mma16816(acc[0][t], aH[0], bb[t]);
                        mma16816(acc[1][t], aH[1], bb[t]);
                    }
            }

            // store prefetched chunk to other buffer
            if (kc < 7) {
                char* dstb = sm + OFF_U + ((kc + 1) & 1) * 25600;
#pragma unroll
                for (int s = 0; s < 4; s++) {
                    int i = tid + s * 512;
                    if (i < 1600) {
                        int split = i >= 800, ii = i - split * 800;
                        int n = ii >> 2, g = ii & 3;
                        *(uint4*)(dstb + split * 12800 + boff(n, g)) = pf[s];
                    }
                }
            }
            __syncthreads();
        }

        // ---- write accumulators straight to g_P (no barriers) ----
#pragma unroll
        for (int i = 0; i < 2; i++)
#pragma unroll
            for (int t = 0; t < 7; t++)
                if (t < 6 || wn == 0) {
                    int col = (wn + 4 * t) * 8 + 2 * (lane & 3);
                    int r0 = wm * 32 + i * 16 + (lane >> 2);
                    size_t base0 = (size_t)(rbase + r0) * NPAR + nbase + col;
                    size_t base1 = (size_t)(rbase + r0 + 8) * NPAR + nbase + col;
                    *(float2*)&g_P[base0] = make_float2(acc[i][t][0], acc[i][t][1]);
                    *(float2*)&g_P[base1] = make_float2(acc[i][t][2], acc[i][t][3]);
                }
    }
}

// ---------------------------------------------------------------------------
// kspline: warp = row, lane = channel (proven round-1 kernel)
// ---------------------------------------------------------------------------
__global__ __launch_bounds__(256, 4)
void kspline(const float* __restrict__ X,
             const float* __restrict__ b2,
             float* __restrict__ out, int B)
{
    const int row  = blockIdx.x * 8 + (threadIdx.x >> 5);
    const int lane = threadIdx.x & 31;

    const float* xr = X + (size_t)row * D_IN;
    out[(size_t)row * D_IN + lane] = xr[lane];          // identity

    const float x = xr[32 + lane];

    const float* pp = g_P + (size_t)row * NPAR + lane * 25;
    const float* bp = b2 + lane * 25;
    float pr[25];
#pragma unroll
    for (int j = 0; j < 25; j++) pr[j] = pp[j] + bp[j];

    // widths
    float mw = pr[0];
#pragma unroll
    for (int j = 1; j < 8; j++) mw = fmaxf(mw, pr[j]);
    float ew[8], sw = 0.f;
#pragma unroll
    for (int j = 0; j < 8; j++) { ew[j] = expf(pr[j] - mw); sw += ew[j]; }
    float invw = 1.f / sw;
    float w[8];
#pragma unroll
    for (int j = 0; j < 8; j++) w[j] = MINW + (1.f - MINW * 8.f) * ew[j] * invw;
    float cw[9]; cw[0] = 0.f;
#pragma unroll
    for (int j = 0; j < 8; j++) cw[j + 1] = cw[j] + w[j];
    float itw = 1.f / fmaxf(cw[8], EPSC);
#pragma unroll
    for (int j = 0; j < 9; j++) cw[j] *= itw;
#pragma unroll
    for (int j = 0; j < 8; j++) w[j] = cw[j + 1] - cw[j];

    // heights
    float mh = pr[8];
#pragma unroll
    for (int j = 1; j < 8; j++) mh = fmaxf(mh, pr[8 + j]);
    float eh[8], sh = 0.f;
#pragma unroll
    for (int j = 0; j < 8; j++) { eh[j] = expf(pr[8 + j] - mh); sh += eh[j]; }
    float invh = 1.f / sh;
    float h[8];
#pragma unroll
    for (int j = 0; j < 8; j++) h[j] = MINW + (1.f - MINW * 8.f) * eh[j] * invh;
    float chh[9]; chh[0] = 0.f;
#pragma unroll
    for (int j = 0; j < 8; j++) chh[j + 1] = chh[j] + h[j];
    float ith = 1.f / fmaxf(chh[8], EPSC);
#pragma unroll
    for (int j = 0; j < 9; j++) chh[j] *= ith;
#pragma unroll
    for (int j = 0; j < 8; j++) h[j] = chh[j + 1] - chh[j];

    // derivatives
    float d[9];
#pragma unroll
    for (int j = 0; j < 9; j++) {
        float u = pr[16 + j];
        d[j] = MIND + fmaxf(u, 0.f) + log1pf(expf(-fabsf(u)));
    }

    const bool inside = (x >= -10.f) && (x <= 10.f);
    float xs = fminf(fmaxf((x + 10.f) * 0.05f, 0.f), 1.f);

    float xk = cw[0], wk = w[0], yk = chh[0], hk = h[0], dk = d[0], dk1 = d[1];
#pragma unroll
    for (int i = 0; i < 8; i++) {
        if (xs >= cw[i]) {
            xk = cw[i]; wk = w[i]; yk = chh[i]; hk = h[i]; dk = d[i]; dk1 = d[i + 1];
        }
    }

    float t   = fminf(fmaxf((xs - xk) / (wk + EPSC), 0.f), 1.f);
    float a   = (hk + EPSC) / (wk + EPSC);
    float omt = 1.f - t;
    float num = a * t * t + dk * t * omt;
    float den = a + (dk + dk1 - 2.f * a) * t * omt;
    float s   = num / (den + EPSC);
    float y   = (yk + hk * s) * 20.f - 10.f;
    float dnum = a * a * (dk1 * t * t + 2.f * a * t * omt + dk * omt * omt);
    float dydx = dnum / (den * den + EPSC);
    float lad  = logf(fmaxf(dydx, 1e-12f));

    float yout = inside ? y : x;
    float ladc = inside ? lad : 0.f;

    out[(size_t)row * D_IN + 32 + lane] = yout;

#pragma unroll
    for (int o = 16; o; o >>= 1)
        ladc += __shfl_xor_sync(0xffffffffu, ladc, o);
    if (lane == 0) out[(size_t)B * D_IN + row] = ladc;
}

// ---------------------------------------------------------------------------
extern "C" void kernel_launch(void* const* d_in, const int* in_sizes, int n_in,
                              void* d_out, int out_size)
{
    const float* X  = (const float*)d_in[0];
    const float* W1 = (const float*)d_in[1];
    const float* b1 = (const float*)d_in[2];
    const float* W2 = (const float*)d_in[3];
    const float* b2 = (const float*)d_in[4];
    float* out = (float*)d_out;

    const int B = in_sizes[0] / D_IN;

    cudaFuncSetAttribute(kgemm, cudaFuncAttributeMaxDynamicSharedMemorySize, SMEM_TOT);

    kprep<<<NPAR + HID, 256>>>(W1, W2);
    kgemm<<<B / 128, 512, SMEM_TOT>>>(X, b1, B);
    kspline<<<B / 8, 256>>>(X, b2, out, B);
}

// round 7
// speedup vs baseline: 1.6704x; 1.6704x over previous
#include <cuda_runtime.h>
#include <cuda_fp16.h>
#include <math.h>
#include <stdint.h>

// ---------------------------------------------------------------------------
// Problem constants
// ---------------------------------------------------------------------------
#define D_IN   64
#define HID    256
#define NPAR   800
#define MINW   0.001f
#define MIND   0.001f
#define EPSC   1e-12f

// Prepared weights: W1 fp16 hi/lo split; W2 fp16 hi ONLY (2-term scheme)
__device__ __half g_W1h[HID * 32],  g_W1l[HID * 32];
__device__ __half g_W2h[NPAR * HID];

// ---------------------------------------------------------------------------
// smem layout (bytes)
// ---------------------------------------------------------------------------
#define OFF_AH   0                    // A (H) hi : 128 rows x 512B (swizzled)
#define OFF_AL   65536                // A lo
#define OFF_U    131072               // union region, 51200 B
//   phase1: XH@U+0 (8192), XL@U+8192, W1H@U+16384, W1L@U+32768
//   phase2: W2 hi k64 chunks, double buffer 2 x 25600
//   epilogue: stage 64 rows x 200 f = 51200
#define BUFSZ    25600
#define OFF_B2   182272               // 800 f
#define OFF_B1   185472               // 256 f
#define OFF_LAD  186496               // 128 f
#define SMEM_TOT 187008

// ---------------------------------------------------------------------------
// helpers
// ---------------------------------------------------------------------------
__device__ __forceinline__ uint32_t smem_u32(const void* p) {
    uint32_t a;
    asm("{ .reg .u64 t; cvta.to.shared.u64 t, %1; cvt.u32.u64 %0, t; }" : "=r"(a) : "l"(p));
    return a;
}
__device__ __forceinline__ void ldsm4(uint32_t r[4], uint32_t addr) {
    asm volatile("ldmatrix.sync.aligned.m8n8.x4.shared.b16 {%0,%1,%2,%3}, [%4];"
                 : "=r"(r[0]), "=r"(r[1]), "=r"(r[2]), "=r"(r[3]) : "r"(addr));
}
__device__ __forceinline__ void mma16816(float c[4], const uint32_t a[4], const uint32_t b[2]) {
    asm volatile("mma.sync.aligned.m16n8k16.row.col.f32.f16.f16.f32 "
                 "{%0,%1,%2,%3}, {%4,%5,%6,%7}, {%8,%9}, {%0,%1,%2,%3};"
                 : "+f"(c[0]), "+f"(c[1]), "+f"(c[2]), "+f"(c[3])
                 : "r"(a[0]), "r"(a[1]), "r"(a[2]), "r"(a[3]), "r"(b[0]), "r"(b[1]));
}
__device__ __forceinline__ uint32_t packh2(float v0, float v1) {
    __half h0 = __float2half_rn(v0), h1 = __float2half_rn(v1);
    return (uint32_t)__half_as_ushort(h0) | ((uint32_t)__half_as_ushort(h1) << 16);
}

// A region (512B rows): byte = r*512 + ((g ^ (r&7))<<4); g = 16B group 0..31
__device__ __forceinline__ uint32_t aoff(int r, int g) {
    return (uint32_t)(r * 512 + ((g ^ (r & 7)) << 4));
}
// 64B-row regions (X, W1t): byte = n*64 + ((g ^ ((n>>1)&3))<<4); g 0..3
__device__ __forceinline__ uint32_t boff(int n, int g) {
    return (uint32_t)(n * 64 + ((g ^ ((n >> 1) & 3)) << 4));
}
// 128B-row regions (W2 k64 chunks): byte = n*128 + ((g ^ (n&7))<<4); g 0..7
__device__ __forceinline__ uint32_t doff(int n, int g) {
    return (uint32_t)(n * 128 + ((g ^ (n & 7)) << 4));
}

// ---------------------------------------------------------------------------
// prep: transpose; W1 split hi/lo; W2 hi only
// ---------------------------------------------------------------------------
__global__ void kprep(const float* __restrict__ W1, const float* __restrict__ W2) {
    int n = blockIdx.x, k = threadIdx.x;
    if (n < NPAR) {
        g_W2h[n * HID + k] = __float2half_rn(W2[(size_t)k * NPAR + n]);
    } else {
        int nn = n - NPAR;
        if (k < 32) {
            float v = W1[k * HID + nn];
            __half h = __float2half_rn(v);
            g_W1h[nn * 32 + k] = h;
            g_W1l[nn * 32 + k] = __float2half_rn(v - __half2float(h));
        }
    }
}

// ---------------------------------------------------------------------------
// fused kernel: 512 threads, 128 rows per CTA
// ---------------------------------------------------------------------------
__global__ __launch_bounds__(512, 1)
void kmain(const float* __restrict__ X,
           const float* __restrict__ b1,
           const float* __restrict__ b2,
           float* __restrict__ out, int B)
{
    extern __shared__ char sm[];
    const uint32_t sb = smem_u32(sm);
    const int tid = threadIdx.x, lane = tid & 31, wid = tid >> 5;
    const int wm = wid >> 2, wn = wid & 3;
    const int rbase = blockIdx.x * 128;

    float* b1s   = (float*)(sm + OFF_B1);
    float* b2s   = (float*)(sm + OFF_B2);
    float* lad   = (float*)(sm + OFF_LAD);
    float* stage = (float*)(sm + OFF_U);

    // ---- init ----
    if (tid < 256) b1s[tid] = b1[tid];
    for (int i = tid; i < NPAR; i += 512) b2s[i] = b2[i];
    if (tid < 128) lad[tid] = 0.f;
    // identity copy (cols 0..31)
    for (int i = tid; i < 1024; i += 512) {
        int r = i >> 3, q = i & 7;
        ((float4*)(out + (size_t)(rbase + r) * D_IN))[q] =
            ((const float4*)(X + (size_t)(rbase + r) * D_IN))[q];
    }

    // ---- phase-1 operand staging: X split + W1t ----
    {
        int r = tid >> 2, q = tid & 3;
        const float* xp = X + (size_t)(rbase + r) * D_IN + q * 8;
        float4 v0 = *(const float4*)xp, v1 = *(const float4*)(xp + 4);
        float vv[8] = {v0.x, v0.y, v0.z, v0.w, v1.x, v1.y, v1.z, v1.w};
        ushort hh[8], hl[8];
#pragma unroll
        for (int j = 0; j < 8; j++) {
            __half h = __float2half_rn(vv[j]);
            hh[j] = __half_as_ushort(h);
            hl[j] = __half_as_ushort(__float2half_rn(vv[j] - __half2float(h)));
        }
        uint32_t off = boff(r, q);
        *(uint4*)(sm + OFF_U + off)        = *(uint4*)hh;   // XH
        *(uint4*)(sm + OFF_U + 8192 + off) = *(uint4*)hl;   // XL
    }
#pragma unroll
    for (int s = 0; s < 4; s++) {
        int i = tid + s * 512;          // 2048 = 2 splits x 256 rows x 4 groups
        int split = i >> 10, ii = i & 1023;
        int n = ii >> 2, g = ii & 3;
        const __half* src = split ? g_W1l : g_W1h;
        uint4 v = *(const uint4*)(src + n * 32 + g * 8);
        *(uint4*)(sm + OFF_U + 16384 + split * 16384 + boff(n, g)) = v;
    }
    __syncthreads();

    // ---- phase-1 mma: H = relu(X @ W1 + b1), warp tile m32 x n64, 3-term ----
    float acc1[2][8][4];
#pragma unroll
    for (int i = 0; i < 2; i++)
#pragma unroll
        for (int j = 0; j < 8; j++)
#pragma unroll
            for (int c = 0; c < 4; c++) acc1[i][j][c] = 0.f;

#pragma unroll
    for (int t = 0; t < 2; t++) {
        uint32_t aH[2][4], aL[2][4], bb[8][2];
#pragma unroll
        for (int i = 0; i < 2; i++) {
            int r = wm * 32 + i * 16 + (lane & 15);
            int g = 2 * t + (lane >> 4);
            ldsm4(aH[i], sb + OFF_U + boff(r, g));          // XH
            ldsm4(aL[i], sb + OFF_U + 8192 + boff(r, g));   // XL
        }
#pragma unroll
        for (int p = 0; p < 4; p++) {
            int jj = wn * 8 + ((lane < 16) ? 2 * p : 2 * p + 1);
            int n = jj * 8 + (lane & 7);
            int g = 2 * t + ((lane >> 3) & 1);
            uint32_t r4[4];
            ldsm4(r4, sb + OFF_U + 16384 + boff(n, g));     // W1H
            bb[2 * p][0] = r4[0]; bb[2 * p][1] = r4[1];
            bb[2 * p + 1][0] = r4[2]; bb[2 * p + 1][1] = r4[3];
        }
#pragma unroll
        for (int i = 0; i < 2; i++)
#pragma unroll
            for (int j = 0; j < 8; j++) {
                mma16816(acc1[i][j], aH[i], bb[j]);
                mma16816(acc1[i][j], aL[i], bb[j]);
            }
#pragma unroll
        for (int p = 0; p < 4; p++) {
            int jj = wn * 8 + ((lane < 16) ? 2 * p : 2 * p + 1);
            int n = jj * 8 + (lane & 7);
            int g = 2 * t + ((lane >> 3) & 1);
            uint32_t r4[4];
            ldsm4(r4, sb + OFF_U + 32768 + boff(n, g));     // W1L
            bb[2 * p][0] = r4[0]; bb[2 * p][1] = r4[1];
            bb[2 * p + 1][0] = r4[2]; bb[2 * p + 1][1] = r4[3];
        }
#pragma unroll
        for (int i = 0; i < 2; i++)
#pragma unroll
            for (int j = 0; j < 8; j++)
                mma16816(acc1[i][j], aH[i], bb[j]);
    }

    // ---- phase-1 epilogue: +b1, relu, fp16-split into A region ----
#pragma unroll
    for (int i = 0; i < 2; i++)
#pragma unroll
        for (int j = 0; j < 8; j++) {
            int col = wn * 64 + j * 8 + 2 * (lane & 3);
            float bv0 = b1s[col], bv1 = b1s[col + 1];
            int r0 = wm * 32 + i * 16 + (lane >> 2);
#pragma unroll
            for (int half = 0; half < 2; half++) {
                int r = r0 + half * 8;
                float v0 = fmaxf(acc1[i][j][2 * half] + bv0, 0.f);
                float v1 = fmaxf(acc1[i][j][2 * half + 1] + bv1, 0.f);
                __half h0 = __float2half_rn(v0), h1 = __float2half_rn(v1);
                uint32_t hi = (uint32_t)__half_as_ushort(h0) |
                              ((uint32_t)__half_as_ushort(h1) << 16);
                uint32_t lo = packh2(v0 - __half2float(h0), v1 - __half2float(h1));
                uint32_t off = aoff(r, col >> 3) + (col & 7) * 2;
                *(uint32_t*)(sm + OFF_AH + off) = hi;
                *(uint32_t*)(sm + OFF_AL + off) = lo;
            }
        }
    __syncthreads();

    // ---- phase-2: P = (Ah+Al) @ W2h per 200-col N-tile (4 tiles) ----
    for (int nt = 0; nt < 4; nt++) {
        const int nbase = nt * 200;
        float acc[2][7][4];
#pragma unroll
        for (int i = 0; i < 2; i++)
#pragma unroll
            for (int t = 0; t < 7; t++)
#pragma unroll
                for (int c = 0; c < 4; c++) acc[i][t][c] = 0.f;

        // load chunk 0 (k64 hi): 200 rows x 8 uint4
#pragma unroll
        for (int s = 0; s < 4; s++) {
            int i = tid + s * 512;
            if (i < 1600) {
                int n = i >> 3, g = i & 7;
                uint4 v = *(const uint4*)(g_W2h + (size_t)(nbase + n) * HID + g * 8);
                *(uint4*)(sm + OFF_U + doff(n, g)) = v;
            }
        }
        __syncthreads();

        for (int kc = 0; kc < 4; kc++) {
            const uint32_t buf = OFF_U + (kc & 1) * BUFSZ;

            // LDG-prefetch next k64 chunk
            uint4 pf[4];
            if (kc < 3) {
#pragma unroll
                for (int s = 0; s < 4; s++) {
                    int i = tid + s * 512;
                    if (i < 1600) {
                        int n = i >> 3, g = i & 7;
                        pf[s] = *(const uint4*)(g_W2h + (size_t)(nbase + n) * HID +
                                                (kc + 1) * 64 + g * 8);
                    }
                }
            }

#pragma unroll
            for (int tt = 0; tt < 4; tt++) {
                const int tg = kc * 4 + tt;
                uint32_t aH[2][4], aL[2][4], bb[7][2];
#pragma unroll
                for (int i = 0; i < 2; i++) {
                    int r = wm * 32 + i * 16 + (lane & 15);
                    int g = 2 * tg + (lane >> 4);
                    ldsm4(aH[i], sb + OFF_AH + aoff(r, g));
                }
#pragma unroll
                for (int p = 0; p < 4; p++) {
                    int ta = 2 * p, tb2 = (2 * p + 1 < 7) ? 2 * p + 1 : 6;
                    int t = (lane < 16) ? ta : tb2;
                    int j = wn + 4 * t; if (j > 24) j = 24;
                    int n = j * 8 + (lane & 7);
                    int g = 2 * tt + ((lane >> 3) & 1);
                    uint32_t r4[4];
                    ldsm4(r4, sb + buf + doff(n, g));
                    bb[ta][0] = r4[0]; bb[ta][1] = r4[1];
                    if (2 * p + 1 < 7) { bb[2 * p + 1][0] = r4[2]; bb[2 * p + 1][1] = r4[3]; }
                }
#pragma unroll
                for (int t = 0; t < 7; t++)
                    if (t < 6 || wn == 0) {
                        mma16816(acc[0][t], aH[0], bb[t]);
                        mma16816(acc[1][t], aH[1], bb[t]);
                    }
#pragma unroll
                for (int i = 0; i < 2; i++) {
                    int r = wm * 32 + i * 16 + (lane & 15);
                    int g = 2 * tg + (lane >> 4);
                    ldsm4(aL[i], sb + OFF_AL + aoff(r, g));
                }
#pragma unroll
                for (int t = 0; t < 7; t++)
                    if (t < 6 || wn == 0) {
                        mma16816(acc[0][t], aL[0], bb[t]);
                        mma16816(acc[1][t], aL[1], bb[t]);
                    }
            }

            // store prefetched chunk to other buffer
            if (kc < 3) {
                char* dstb = sm + OFF_U + ((kc + 1) & 1) * BUFSZ;
#pragma unroll
                for (int s = 0; s < 4; s++) {
                    int i = tid + s * 512;
                    if (i < 1600) {
                        int n = i >> 3, g = i & 7;
                        *(uint4*)(dstb + doff(n, g)) = pf[s];
                    }
                }
            }
            __syncthreads();
        }

        // ---- epilogue: stage 64 rows at a time, then spline ----
        for (int mh = 0; mh < 2; mh++) {
            if ((wm >> 1) == mh) {
                int rloc = (wm & 1) * 32;
#pragma unroll
                for (int i = 0; i < 2; i++)
#pragma unroll
                    for (int t = 0; t < 7; t++)
                        if (t < 6 || wn == 0) {
                            int col = (wn + 4 * t) * 8 + 2 * (lane & 3);
                            int r0 = rloc + i * 16 + (lane >> 2);
                            *(float2*)&stage[r0 * 200 + col] =
                                make_float2(acc[i][t][0], acc[i][t][1]);
                            *(float2*)&stage[(r0 + 8) * 200 + col] =
                                make_float2(acc[i][t][2], acc[i][t][3]);
                        }
            }
            __syncthreads();

            {
                const int rl = tid >> 3, lc = tid & 7;   // 64 rows x 8 channels
                const int ch = nt * 8 + lc;
                const float* sp = &stage[rl * 200 + lc * 25];
                const float* bp = &b2s[ch * 25];
                float pr[25];
#pragma unroll
                for (int j = 0; j < 25; j++) pr[j] = sp[j] + bp[j];

                // widths
                float mw = pr[0];
#pragma unroll
                for (int j = 1; j < 8; j++) mw = fmaxf(mw, pr[j]);
                float ew[8], sw = 0.f;
#pragma unroll
                for (int j = 0; j < 8; j++) { ew[j] = expf(pr[j] - mw); sw += ew[j]; }
                float invw = 1.f / sw;
                float w[8];
#pragma unroll
                for (int j = 0; j < 8; j++) w[j] = MINW + (1.f - MINW * 8.f) * ew[j] * invw;
                float cw[9]; cw[0] = 0.f;
#pragma unroll
                for (int j = 0; j < 8; j++) cw[j + 1] = cw[j] + w[j];
                float itw = 1.f / fmaxf(cw[8], EPSC);
#pragma unroll
                for (int j = 0; j < 9; j++) cw[j] *= itw;
#pragma unroll
                for (int j = 0; j < 8; j++) w[j] = cw[j + 1] - cw[j];

                // heights
                float mhh = pr[8];
#pragma unroll
                for (int j = 1; j < 8; j++) mhh = fmaxf(mhh, pr[8 + j]);
                float eh[8], sh = 0.f;
#pragma unroll
                for (int j = 0; j < 8; j++) { eh[j] = expf(pr[8 + j] - mhh); sh += eh[j]; }
                float invh = 1.f / sh;
                float hh[8];
#pragma unroll
                for (int j = 0; j < 8; j++) hh[j] = MINW + (1.f - MINW * 8.f) * eh[j] * invh;
                float chh[9]; chh[0] = 0.f;
#pragma unroll
                for (int j = 0; j < 8; j++) chh[j + 1] = chh[j] + hh[j];
                float ith = 1.f / fmaxf(chh[8], EPSC);
#pragma unroll
                for (int j = 0; j < 9; j++) chh[j] *= ith;
#pragma unroll
                for (int j = 0; j < 8; j++) hh[j] = chh[j + 1] - chh[j];

                // derivatives (softplus)
                float d[9];
#pragma unroll
                for (int j = 0; j < 9; j++) {
                    float u = pr[16 + j];
                    d[j] = MIND + fmaxf(u, 0.f) + log1pf(expf(-fabsf(u)));
                }

                const int grow = rbase + mh * 64 + rl;
                const float x = X[(size_t)grow * D_IN + 32 + ch];
                const bool inside = (x >= -10.f) && (x <= 10.f);
                float xs = fminf(fmaxf((x + 10.f) * 0.05f, 0.f), 1.f);

                float xk = cw[0], wk = w[0], yk = chh[0], hk = hh[0], dk = d[0], dk1 = d[1];
#pragma unroll
                for (int i = 0; i < 8; i++) {
                    if (xs >= cw[i]) {
                        xk = cw[i]; wk = w[i]; yk = chh[i]; hk = hh[i];
                        dk = d[i]; dk1 = d[i + 1];
                    }
                }
                float t   = fminf(fmaxf((xs - xk) / (wk + EPSC), 0.f), 1.f);
                float a   = (hk + EPSC) / (wk + EPSC);
                float omt = 1.f - t;
                float num = a * t * t + dk * t * omt;
                float den = a + (dk + dk1 - 2.f * a) * t * omt;
                float s   = num / (den + EPSC);
                float y   = (yk + hk * s) * 20.f - 10.f;
                float dnum = a * a * (dk1 * t * t + 2.f * a * t * omt + dk * omt * omt);
                float dydx = dnum / (den * den + EPSC);
                float ladv = logf(fmaxf(dydx, 1e-12f));

                out[(size_t)grow * D_IN + 32 + ch] = inside ? y : x;
                float lv = inside ? ladv : 0.f;
                lv += __shfl_xor_sync(0xffffffffu, lv, 1);
                lv += __shfl_xor_sync(0xffffffffu, lv, 2);
                lv += __shfl_xor_sync(0xffffffffu, lv, 4);
                if ((lane & 7) == 0) lad[mh * 64 + rl] += lv;
            }
            __syncthreads();
        }
    }

    if (tid < 128) out[(size_t)B * D_IN + rbase + tid] = lad[tid];
}

// ---------------------------------------------------------------------------
extern "C" void kernel_launch(void* const* d_in, const int* in_sizes, int n_in,
                              void* d_out, int out_size)
{
    const float* X  = (const float*)d_in[0];
    const float* W1 = (const float*)d_in[1];
    const float* b1 = (const float*)d_in[2];
    const float* W2 = (const float*)d_in[3];
    const float* b2 = (const float*)d_in[4];
    float* out = (float*)d_out;

    const int B = in_sizes[0] / D_IN;

    cudaFuncSetAttribute(kmain, cudaFuncAttributeMaxDynamicSharedMemorySize, SMEM_TOT);

    kprep<<<NPAR + HID, 256>>>(W1, W2);
    kmain<<<B / 128, 512, SMEM_TOT>>>(X, b1, b2, out, B);
}

// round 8
// speedup vs baseline: 2.0804x; 1.2455x over previous
#include <cuda_runtime.h>
#include <cuda_fp16.h>
#include <math.h>
#include <stdint.h>

// ---------------------------------------------------------------------------
// Problem constants
// ---------------------------------------------------------------------------
#define D_IN   64
#define HID    256
#define NPAR   800
#define MINW   0.001f
#define MIND   0.001f
#define EPSC   1e-12f

// Prepared weights: W1 fp16 hi/lo split; W2 fp16 fragment-ordered for LDG
__device__ __half g_W1h[HID * 32], g_W1l[HID * 32];
// g_W2p[tile J=0..99][kgroup q=0..15][lane 0..31] = {b0,b1} fragment words
__device__ uint2  g_W2p[100 * 16 * 32];

// ---------------------------------------------------------------------------
// smem layout (bytes) — identical to round 7
// ---------------------------------------------------------------------------
#define OFF_AH   0                    // A (H) hi : 128 rows x 512B (swizzled)
#define OFF_AL   65536                // A lo
#define OFF_U    131072               // union: phase1 staging / epilogue stage
#define OFF_B2   182272               // 800 f
#define OFF_B1   185472               // 256 f
#define OFF_LAD  186496               // 128 f
#define SMEM_TOT 187008

// ---------------------------------------------------------------------------
// helpers
// ---------------------------------------------------------------------------
__device__ __forceinline__ uint32_t smem_u32(const void* p) {
    uint32_t a;
    asm("{ .reg .u64 t; cvta.to.shared.u64 t, %1; cvt.u32.u64 %0, t; }" : "=r"(a) : "l"(p));
    return a;
}
__device__ __forceinline__ void ldsm4(uint32_t r[4], uint32_t addr) {
    asm volatile("ldmatrix.sync.aligned.m8n8.x4.shared.b16 {%0,%1,%2,%3}, [%4];"
                 : "=r"(r[0]), "=r"(r[1]), "=r"(r[2]), "=r"(r[3]) : "r"(addr));
}
__device__ __forceinline__ void mma16816(float c[4], const uint32_t a[4], const uint32_t b[2]) {
    asm volatile("mma.sync.aligned.m16n8k16.row.col.f32.f16.f16.f32 "
                 "{%0,%1,%2,%3}, {%4,%5,%6,%7}, {%8,%9}, {%0,%1,%2,%3};"
                 : "+f"(c[0]), "+f"(c[1]), "+f"(c[2]), "+f"(c[3])
                 : "r"(a[0]), "r"(a[1]), "r"(a[2]), "r"(a[3]), "r"(b[0]), "r"(b[1]));
}
__device__ __forceinline__ uint32_t packh2(float v0, float v1) {
    __half h0 = __float2half_rn(v0), h1 = __float2half_rn(v1);
    return (uint32_t)__half_as_ushort(h0) | ((uint32_t)__half_as_ushort(h1) << 16);
}

// A region (512B rows): byte = r*512 + ((g ^ (r&7))<<4); g = 16B group 0..31
__device__ __forceinline__ uint32_t aoff(int r, int g) {
    return (uint32_t)(r * 512 + ((g ^ (r & 7)) << 4));
}
// 64B-row regions (X, W1t): byte = n*64 + ((g ^ ((n>>1)&3))<<4); g 0..3
__device__ __forceinline__ uint32_t boff(int n, int g) {
    return (uint32_t)(n * 64 + ((g ^ ((n >> 1) & 3)) << 4));
}

// ---------------------------------------------------------------------------
// prep: W1 transpose + hi/lo split
// ---------------------------------------------------------------------------
__global__ void kprepW1(const float* __restrict__ W1) {
    int nn = blockIdx.x, k = threadIdx.x;   // nn 0..255, k 0..31
    float v = W1[k * HID + nn];
    __half h = __float2half_rn(v);
    g_W1h[nn * 32 + k] = h;
    g_W1l[nn * 32 + k] = __float2half_rn(v - __half2float(h));
}

// prep: W2 -> fragment-ordered fp16, one block per (tile J, kgroup q)
__global__ void kprepW2(const float* __restrict__ W2) {
    int J = blockIdx.x >> 4, q = blockIdx.x & 15, l = threadIdx.x;   // l 0..31
    int n  = J * 8 + (l >> 2);
    int k0 = q * 16 + (l & 3) * 2;
    uint32_t w0 = packh2(W2[(size_t)k0 * NPAR + n],       W2[(size_t)(k0 + 1) * NPAR + n]);
    uint32_t w1 = packh2(W2[(size_t)(k0 + 8) * NPAR + n], W2[(size_t)(k0 + 9) * NPAR + n]);
    g_W2p[(size_t)blockIdx.x * 32 + l] = make_uint2(w0, w1);
}

// ---------------------------------------------------------------------------
// fused kernel: 512 threads, 128 rows per CTA
// ---------------------------------------------------------------------------
__global__ __launch_bounds__(512, 1)
void kmain(const float* __restrict__ X,
           const float* __restrict__ b1,
           const float* __restrict__ b2,
           float* __restrict__ out, int B)
{
    extern __shared__ char sm[];
    const uint32_t sb = smem_u32(sm);
    const int tid = threadIdx.x, lane = tid & 31, wid = tid >> 5;
    const int wm = wid >> 2, wn = wid & 3;
    const int rbase = blockIdx.x * 128;

    float* b1s   = (float*)(sm + OFF_B1);
    float* b2s   = (float*)(sm + OFF_B2);
    float* lad   = (float*)(sm + OFF_LAD);
    float* stage = (float*)(sm + OFF_U);

    // ---- init ----
    if (tid < 256) b1s[tid] = b1[tid];
    for (int i = tid; i < NPAR; i += 512) b2s[i] = b2[i];
    if (tid < 128) lad[tid] = 0.f;
    for (int i = tid; i < 1024; i += 512) {          // identity copy
        int r = i >> 3, q = i & 7;
        ((float4*)(out + (size_t)(rbase + r) * D_IN))[q] =
            ((const float4*)(X + (size_t)(rbase + r) * D_IN))[q];
    }

    // ---- phase-1 operand staging: X split + W1t ----
    {
        int r = tid >> 2, q = tid & 3;
        const float* xp = X + (size_t)(rbase + r) * D_IN + q * 8;
        float4 v0 = *(const float4*)xp, v1 = *(const float4*)(xp + 4);
        float vv[8] = {v0.x, v0.y, v0.z, v0.w, v1.x, v1.y, v1.z, v1.w};
        ushort hh[8], hl[8];
#pragma unroll
        for (int j = 0; j < 8; j++) {
            __half h = __float2half_rn(vv[j]);
            hh[j] = __half_as_ushort(h);
            hl[j] = __half_as_ushort(__float2half_rn(vv[j] - __half2float(h)));
        }
        uint32_t off = boff(r, q);
        *(uint4*)(sm + OFF_U + off)        = *(uint4*)hh;
        *(uint4*)(sm + OFF_U + 8192 + off) = *(uint4*)hl;
    }
#pragma unroll
    for (int s = 0; s < 4; s++) {
        int i = tid + s * 512;
        int split = i >> 10, ii = i & 1023;
        int n = ii >> 2, g = ii & 3;
        const __half* src = split ? g_W1l : g_W1h;
        uint4 v = *(const uint4*)(src + n * 32 + g * 8);
        *(uint4*)(sm + OFF_U + 16384 + split * 16384 + boff(n, g)) = v;
    }
    __syncthreads();

    // ---- phase-1 mma: H = relu(X @ W1 + b1) ----
    float acc1[2][8][4];
#pragma unroll
    for (int i = 0; i < 2; i++)
#pragma unroll
        for (int j = 0; j < 8; j++)
#pragma unroll
            for (int c = 0; c < 4; c++) acc1[i][j][c] = 0.f;

#pragma unroll
    for (int t = 0; t < 2; t++) {
        uint32_t aH[2][4], aL[2][4], bb[8][2];
#pragma unroll
        for (int i = 0; i < 2; i++) {
            int r = wm * 32 + i * 16 + (lane & 15);
            int g = 2 * t + (lane >> 4);
            ldsm4(aH[i], sb + OFF_U + boff(r, g));
            ldsm4(aL[i], sb + OFF_U + 8192 + boff(r, g));
        }
#pragma unroll
        for (int p = 0; p < 4; p++) {
            int jj = wn * 8 + ((lane < 16) ? 2 * p : 2 * p + 1);
            int n = jj * 8 + (lane & 7);
            int g = 2 * t + ((lane >> 3) & 1);
            uint32_t r4[4];
            ldsm4(r4, sb + OFF_U + 16384 + boff(n, g));
            bb[2 * p][0] = r4[0]; bb[2 * p][1] = r4[1];
            bb[2 * p + 1][0] = r4[2]; bb[2 * p + 1][1] = r4[3];
        }
#pragma unroll
        for (int i = 0; i < 2; i++)
#pragma unroll
            for (int j = 0; j < 8; j++) {
                mma16816(acc1[i][j], aH[i], bb[j]);
                mma16816(acc1[i][j], aL[i], bb[j]);
            }
#pragma unroll
        for (int p = 0; p < 4; p++) {
            int jj = wn * 8 + ((lane < 16) ? 2 * p : 2 * p + 1);
            int n = jj * 8 + (lane & 7);
            int g = 2 * t + ((lane >> 3) & 1);
            uint32_t r4[4];
            ldsm4(r4, sb + OFF_U + 32768 + boff(n, g));
            bb[2 * p][0] = r4[0]; bb[2 * p][1] = r4[1];
            bb[2 * p + 1][0] = r4[2]; bb[2 * p + 1][1] = r4[3];
        }
#pragma unroll
        for (int i = 0; i < 2; i++)
#pragma unroll
            for (int j = 0; j < 8; j++)
                mma16816(acc1[i][j], aH[i], bb[j]);
    }

    // ---- phase-1 epilogue: +b1, relu, fp16-split into A region ----
#pragma unroll
    for (int i = 0; i < 2; i++)
#pragma unroll
        for (int j = 0; j < 8; j++) {
            int col = wn * 64 + j * 8 + 2 * (lane & 3);
            float bv0 = b1s[col], bv1 = b1s[col + 1];
            int r0 = wm * 32 + i * 16 + (lane >> 2);
#pragma unroll
            for (int half = 0; half < 2; half++) {
                int r = r0 + half * 8;
                float v0 = fmaxf(acc1[i][j][2 * half] + bv0, 0.f);
                float v1 = fmaxf(acc1[i][j][2 * half + 1] + bv1, 0.f);
                __half h0 = __float2half_rn(v0), h1 = __float2half_rn(v1);
                uint32_t hi = (uint32_t)__half_as_ushort(h0) |
                              ((uint32_t)__half_as_ushort(h1) << 16);
                uint32_t lo = packh2(v0 - __half2float(h0), v1 - __half2float(h1));
                uint32_t off = aoff(r, col >> 3) + (col & 7) * 2;
                *(uint32_t*)(sm + OFF_AH + off) = hi;
                *(uint32_t*)(sm + OFF_AL + off) = lo;
            }
        }
    __syncthreads();

    // ---- phase-2: barrier-free GEMM, B-fragments via pipelined LDG ----
    for (int nt = 0; nt < 4; nt++) {
        float acc[2][7][4];
#pragma unroll
        for (int i = 0; i < 2; i++)
#pragma unroll
            for (int t = 0; t < 7; t++)
#pragma unroll
                for (int c = 0; c < 4; c++) acc[i][t][c] = 0.f;

        // per-warp B base: tile j = wn + 4t, fragment stream for this lane
        const uint2* bbase = g_W2p + (size_t)(nt * 25 + wn) * 512 + lane;

        uint2 Bq[2][7];
#pragma unroll
        for (int t = 0; t < 7; t++)
            if (wn == 0 || t < 6) Bq[0][t] = bbase[t * 2048];

#pragma unroll
        for (int q = 0; q < 16; q++) {
            const int cur = q & 1, nxt = cur ^ 1;
            if (q < 15) {
#pragma unroll
                for (int t = 0; t < 7; t++)
                    if (wn == 0 || t < 6) Bq[nxt][t] = bbase[t * 2048 + (q + 1) * 32];
            }
            uint32_t aH[2][4], aL[2][4];
#pragma unroll
            for (int i = 0; i < 2; i++) {
                int r = wm * 32 + i * 16 + (lane & 15);
                int g = 2 * q + (lane >> 4);
                ldsm4(aH[i], sb + OFF_AH + aoff(r, g));
            }
#pragma unroll
            for (int t = 0; t < 7; t++)
                if (t < 6 || wn == 0) {
                    const uint32_t* bp = (const uint32_t*)&Bq[cur][t];
                    mma16816(acc[0][t], aH[0], bp);
                    mma16816(acc[1][t], aH[1], bp);
                }
#pragma unroll
            for (int i = 0; i < 2; i++) {
                int r = wm * 32 + i * 16 + (lane & 15);
                int g = 2 * q + (lane >> 4);
                ldsm4(aL[i], sb + OFF_AL + aoff(r, g));
            }
#pragma unroll
            for (int t = 0; t < 7; t++)
                if (t < 6 || wn == 0) {
                    const uint32_t* bp = (const uint32_t*)&Bq[cur][t];
                    mma16816(acc[0][t], aL[0], bp);
                    mma16816(acc[1][t], aL[1], bp);
                }
        }

        // ---- epilogue: stage 64 rows at a time, then spline ----
        for (int mh = 0; mh < 2; mh++) {
            if ((wm >> 1) == mh) {
                int rloc = (wm & 1) * 32;
#pragma unroll
                for (int i = 0; i < 2; i++)
#pragma unroll
                    for (int t = 0; t < 7; t++)
                        if (t < 6 || wn == 0) {
                            int col = (wn + 4 * t) * 8 + 2 * (lane & 3);
                            int r0 = rloc + i * 16 + (lane >> 2);
                            *(float2*)&stage[r0 * 200 + col] =
                                make_float2(acc[i][t][0], acc[i][t][1]);
                            *(float2*)&stage[(r0 + 8) * 200 + col] =
                                make_float2(acc[i][t][2], acc[i][t][3]);
                        }
            }
            __syncthreads();

            {
                const int rl = tid >> 3, lc = tid & 7;   // 64 rows x 8 channels
                const int ch = nt * 8 + lc;
                const float* sp = &stage[rl * 200 + lc * 25];
                const float* bp = &b2s[ch * 25];
                float pr[25];
#pragma unroll
                for (int j = 0; j < 25; j++) pr[j] = sp[j] + bp[j];

                // widths
                float mw = pr[0];
#pragma unroll
                for (int j = 1; j < 8; j++) mw = fmaxf(mw, pr[j]);
                float ew[8], sw = 0.f;
#pragma unroll
                for (int j = 0; j < 8; j++) { ew[j] = __expf(pr[j] - mw); sw += ew[j]; }
                float invw = __fdividef(1.f, sw);
                float w[8];
#pragma unroll
                for (int j = 0; j < 8; j++) w[j] = MINW + (1.f - MINW * 8.f) * ew[j] * invw;
                float cw[9]; cw[0] = 0.f;
#pragma unroll
                for (int j = 0; j < 8; j++) cw[j + 1] = cw[j] + w[j];
                float itw = __fdividef(1.f, fmaxf(cw[8], EPSC));
#pragma unroll
                for (int j = 0; j < 9; j++) cw[j] *= itw;
#pragma unroll
                for (int j = 0; j < 8; j++) w[j] = cw[j + 1] - cw[j];

                // heights
                float mhh = pr[8];
#pragma unroll
                for (int j = 1; j < 8; j++) mhh = fmaxf(mhh, pr[8 + j]);
                float eh[8], sh = 0.f;
#pragma unroll
                for (int j = 0; j < 8; j++) { eh[j] = __expf(pr[8 + j] - mhh); sh += eh[j]; }
                float invh = __fdividef(1.f, sh);
                float hh[8];
#pragma unroll
                for (int j = 0; j < 8; j++) hh[j] = MINW + (1.f - MINW * 8.f) * eh[j] * invh;
                float chh[9]; chh[0] = 0.f;
#pragma unroll
                for (int j = 0; j < 8; j++) chh[j + 1] = chh[j] + hh[j];
                float ith = __fdividef(1.f, fmaxf(chh[8], EPSC));
#pragma unroll
                for (int j = 0; j < 9; j++) chh[j] *= ith;
#pragma unroll
                for (int j = 0; j < 8; j++) hh[j] = chh[j + 1] - chh[j];

                // derivatives (softplus via fast intrinsics)
                float d[9];
#pragma unroll
                for (int j = 0; j < 9; j++) {
                    float u = pr[16 + j];
                    d[j] = MIND + fmaxf(u, 0.f) + __logf(1.f + __expf(-fabsf(u)));
                }

                const int grow = rbase + mh * 64 + rl;
                const float x = X[(size_t)grow * D_IN + 32 + ch];
                const bool inside = (x >= -10.f) && (x <= 10.f);
                float xs = fminf(fmaxf((x + 10.f) * 0.05f, 0.f), 1.f);

                float xk = cw[0], wk = w[0], yk = chh[0], hk = hh[0], dk = d[0], dk1 = d[1];
#pragma unroll
                for (int i = 0; i < 8; i++) {
                    if (xs >= cw[i]) {
                        xk = cw[i]; wk = w[i]; yk = chh[i]; hk = hh[i];
                        dk = d[i]; dk1 = d[i + 1];
                    }
                }
                float t   = fminf(fmaxf(__fdividef(xs - xk, wk + EPSC), 0.f), 1.f);
                float a   = __fdividef(hk + EPSC, wk + EPSC);
                float omt = 1.f - t;
                float num = a * t * t + dk * t * omt;
                float den = a + (dk + dk1 - 2.f * a) * t * omt;
                float s   = __fdividef(num, den + EPSC);
                float y   = (yk + hk * s) * 20.f - 10.f;
                float dnum = a * a * (dk1 * t * t + 2.f * a * t * omt + dk * omt * omt);
                float dydx = __fdividef(dnum, den * den + EPSC);
                float ladv = __logf(fmaxf(dydx, 1e-12f));

                out[(size_t)grow * D_IN + 32 + ch] = inside ? y : x;
                float lv = inside ? ladv : 0.f;
                lv += __shfl_xor_sync(0xffffffffu, lv, 1);
                lv += __shfl_xor_sync(0xffffffffu, lv, 2);
                lv += __shfl_xor_sync(0xffffffffu, lv, 4);
                if ((lane & 7) == 0) lad[mh * 64 + rl] += lv;
            }
            __syncthreads();
        }
    }

    if (tid < 128) out[(size_t)B * D_IN + rbase + tid] = lad[tid];
}

// ---------------------------------------------------------------------------
extern "C" void kernel_launch(void* const* d_in, const int* in_sizes, int n_in,
                              void* d_out, int out_size)
{
    const float* X  = (const float*)d_in[0];
    const float* W1 = (const float*)d_in[1];
    const float* b1 = (const float*)d_in[2];
    const float* W2 = (const float*)d_in[3];
    const float* b2 = (const float*)d_in[4];
    float* out = (float*)d_out;

    const int B = in_sizes[0] / D_IN;

    cudaFuncSetAttribute(kmain, cudaFuncAttributeMaxDynamicSharedMemorySize, SMEM_TOT);

    kprepW1<<<HID, 32>>>(W1);
    kprepW2<<<1600, 32>>>(W2);
    kmain<<<B / 128, 512, SMEM_TOT>>>(X, b1, b2, out, B);
}

// round 9
// speedup vs baseline: 3.1506x; 1.5144x over previous
#include <cuda_runtime.h>
#include <cuda_fp16.h>
#include <math.h>
#include <stdint.h>

// ---------------------------------------------------------------------------
// Problem constants
// ---------------------------------------------------------------------------
#define D_IN   64
#define HID    256
#define NPAR   800
#define MINW   0.001f
#define MIND   0.001f
#define EPSC   1e-12f

// Prepared weights: W1 fp16 hi/lo split (phase-1 stays 3-term);
// W2 fp16 fragment-ordered for direct LDG into mma B-operands.
__device__ __half g_W1h[HID * 32], g_W1l[HID * 32];
// g_W2p[tile J=0..99][kgroup q=0..15][lane 0..31] = {b0,b1} fragment words
__device__ uint2  g_W2p[100 * 16 * 32];

// ---------------------------------------------------------------------------
// smem layout (bytes)
// ---------------------------------------------------------------------------
#define OFF_AH   0                    // A (H) fp16 : 128 rows x 512B (swizzled)
#define OFF_U    65536                // union: phase1 staging (48K) / stage (100K)
#define OFF_B2   167936               // 800 f
#define OFF_B1   171136               // 256 f
#define OFF_LAD  172160               // 128 f
#define SMEM_TOT 172672

// ---------------------------------------------------------------------------
// helpers
// ---------------------------------------------------------------------------
__device__ __forceinline__ uint32_t smem_u32(const void* p) {
    uint32_t a;
    asm("{ .reg .u64 t; cvta.to.shared.u64 t, %1; cvt.u32.u64 %0, t; }" : "=r"(a) : "l"(p));
    return a;
}
__device__ __forceinline__ void ldsm4(uint32_t r[4], uint32_t addr) {
    asm volatile("ldmatrix.sync.aligned.m8n8.x4.shared.b16 {%0,%1,%2,%3}, [%4];"
                 : "=r"(r[0]), "=r"(r[1]), "=r"(r[2]), "=r"(r[3]) : "r"(addr));
}
__device__ __forceinline__ void mma16816(float c[4], const uint32_t a[4], const uint32_t b[2]) {
    asm volatile("mma.sync.aligned.m16n8k16.row.col.f32.f16.f16.f32 "
                 "{%0,%1,%2,%3}, {%4,%5,%6,%7}, {%8,%9}, {%0,%1,%2,%3};"
                 : "+f"(c[0]), "+f"(c[1]), "+f"(c[2]), "+f"(c[3])
                 : "r"(a[0]), "r"(a[1]), "r"(a[2]), "r"(a[3]), "r"(b[0]), "r"(b[1]));
}
__device__ __forceinline__ uint32_t packh2(float v0, float v1) {
    __half h0 = __float2half_rn(v0), h1 = __float2half_rn(v1);
    return (uint32_t)__half_as_ushort(h0) | ((uint32_t)__half_as_ushort(h1) << 16);
}

// A region (512B rows): byte = r*512 + ((g ^ (r&7))<<4); g = 16B group 0..31
__device__ __forceinline__ uint32_t aoff(int r, int g) {
    return (uint32_t)(r * 512 + ((g ^ (r & 7)) << 4));
}
// 64B-row regions (X, W1t): byte = n*64 + ((g ^ ((n>>1)&3))<<4); g 0..3
__device__ __forceinline__ uint32_t boff(int n, int g) {
    return (uint32_t)(n * 64 + ((g ^ ((n >> 1) & 3)) << 4));
}

// ---------------------------------------------------------------------------
// prep kernels
// ---------------------------------------------------------------------------
__global__ void kprepW1(const float* __restrict__ W1) {
    int nn = blockIdx.x, k = threadIdx.x;   // nn 0..255, k 0..31
    float v = W1[k * HID + nn];
    __half h = __float2half_rn(v);
    g_W1h[nn * 32 + k] = h;
    g_W1l[nn * 32 + k] = __float2half_rn(v - __half2float(h));
}

__global__ void kprepW2(const float* __restrict__ W2) {
    int J = blockIdx.x >> 4, q = blockIdx.x & 15, l = threadIdx.x;   // l 0..31
    int n  = J * 8 + (l >> 2);
    int k0 = q * 16 + (l & 3) * 2;
    uint32_t w0 = packh2(W2[(size_t)k0 * NPAR + n],       W2[(size_t)(k0 + 1) * NPAR + n]);
    uint32_t w1 = packh2(W2[(size_t)(k0 + 8) * NPAR + n], W2[(size_t)(k0 + 9) * NPAR + n]);
    g_W2p[(size_t)blockIdx.x * 32 + l] = make_uint2(w0, w1);
}

// ---------------------------------------------------------------------------
// fused kernel: 512 threads, 128 rows per CTA
// ---------------------------------------------------------------------------
__global__ __launch_bounds__(512, 1)
void kmain(const float* __restrict__ X,
           const float* __restrict__ b1,
           const float* __restrict__ b2,
           float* __restrict__ out, int B)
{
    extern __shared__ char sm[];
    const uint32_t sb = smem_u32(sm);
    const int tid = threadIdx.x, lane = tid & 31, wid = tid >> 5;
    const int wm = wid >> 2, wn = wid & 3;
    const int rbase = blockIdx.x * 128;

    float* b1s   = (float*)(sm + OFF_B1);
    float* b2s   = (float*)(sm + OFF_B2);
    float* lad   = (float*)(sm + OFF_LAD);
    float* stage = (float*)(sm + OFF_U);

    // ---- init ----
    if (tid < 256) b1s[tid] = b1[tid];
    for (int i = tid; i < NPAR; i += 512) b2s[i] = b2[i];
    if (tid < 128) lad[tid] = 0.f;
    for (int i = tid; i < 1024; i += 512) {          // identity copy
        int r = i >> 3, q = i & 7;
        ((float4*)(out + (size_t)(rbase + r) * D_IN))[q] =
            ((const float4*)(X + (size_t)(rbase + r) * D_IN))[q];
    }

    // ---- phase-1 operand staging: X split + W1t (in union region) ----
    {
        int r = tid >> 2, q = tid & 3;
        const float* xp = X + (size_t)(rbase + r) * D_IN + q * 8;
        float4 v0 = *(const float4*)xp, v1 = *(const float4*)(xp + 4);
        float vv[8] = {v0.x, v0.y, v0.z, v0.w, v1.x, v1.y, v1.z, v1.w};
        ushort hh[8], hl[8];
#pragma unroll
        for (int j = 0; j < 8; j++) {
            __half h = __float2half_rn(vv[j]);
            hh[j] = __half_as_ushort(h);
            hl[j] = __half_as_ushort(__float2half_rn(vv[j] - __half2float(h)));
        }
        uint32_t off = boff(r, q);
        *(uint4*)(sm + OFF_U + off)        = *(uint4*)hh;   // XH
        *(uint4*)(sm + OFF_U + 8192 + off) = *(uint4*)hl;   // XL
    }
#pragma unroll
    for (int s = 0; s < 4; s++) {
        int i = tid + s * 512;
        int split = i >> 10, ii = i & 1023;
        int n = ii >> 2, g = ii & 3;
        const __half* src = split ? g_W1l : g_W1h;
        uint4 v = *(const uint4*)(src + n * 32 + g * 8);
        *(uint4*)(sm + OFF_U + 16384 + split * 16384 + boff(n, g)) = v;
    }
    __syncthreads();

    // ---- phase-1 mma: H = relu(X @ W1 + b1), 3-term (accurate H) ----
    float acc1[2][8][4];
#pragma unroll
    for (int i = 0; i < 2; i++)
#pragma unroll
        for (int j = 0; j < 8; j++)
#pragma unroll
            for (int c = 0; c < 4; c++) acc1[i][j][c] = 0.f;

#pragma unroll
    for (int t = 0; t < 2; t++) {
        uint32_t aH[2][4], aL[2][4], bb[8][2];
#pragma unroll
        for (int i = 0; i < 2; i++) {
            int r = wm * 32 + i * 16 + (lane & 15);
            int g = 2 * t + (lane >> 4);
            ldsm4(aH[i], sb + OFF_U + boff(r, g));
            ldsm4(aL[i], sb + OFF_U + 8192 + boff(r, g));
        }
#pragma unroll
        for (int p = 0; p < 4; p++) {
            int jj = wn * 8 + ((lane < 16) ? 2 * p : 2 * p + 1);
            int n = jj * 8 + (lane & 7);
            int g = 2 * t + ((lane >> 3) & 1);
            uint32_t r4[4];
            ldsm4(r4, sb + OFF_U + 16384 + boff(n, g));
            bb[2 * p][0] = r4[0]; bb[2 * p][1] = r4[1];
            bb[2 * p + 1][0] = r4[2]; bb[2 * p + 1][1] = r4[3];
        }
#pragma unroll
        for (int i = 0; i < 2; i++)
#pragma unroll
            for (int j = 0; j < 8; j++) {
                mma16816(acc1[i][j], aH[i], bb[j]);
                mma16816(acc1[i][j], aL[i], bb[j]);
            }
#pragma unroll
        for (int p = 0; p < 4; p++) {
            int jj = wn * 8 + ((lane < 16) ? 2 * p : 2 * p + 1);
            int n = jj * 8 + (lane & 7);
            int g = 2 * t + ((lane >> 3) & 1);
            uint32_t r4[4];
            ldsm4(r4, sb + OFF_U + 32768 + boff(n, g));
            bb[2 * p][0] = r4[0]; bb[2 * p][1] = r4[1];
            bb[2 * p + 1][0] = r4[2]; bb[2 * p + 1][1] = r4[3];
        }
#pragma unroll
        for (int i = 0; i < 2; i++)
#pragma unroll
            for (int j = 0; j < 8; j++)
                mma16816(acc1[i][j], aH[i], bb[j]);
    }

    // ---- phase-1 epilogue: +b1, relu, single fp16 into A region ----
#pragma unroll
    for (int i = 0; i < 2; i++)
#pragma unroll
        for (int j = 0; j < 8; j++) {
            int col = wn * 64 + j * 8 + 2 * (lane & 3);
            float bv0 = b1s[col], bv1 = b1s[col + 1];
            int r0 = wm * 32 + i * 16 + (lane >> 2);
#pragma unroll
            for (int half = 0; half < 2; half++) {
                int r = r0 + half * 8;
                float v0 = fmaxf(acc1[i][j][2 * half] + bv0, 0.f);
                float v1 = fmaxf(acc1[i][j][2 * half + 1] + bv1, 0.f);
                uint32_t off = aoff(r, col >> 3) + (col & 7) * 2;
                *(uint32_t*)(sm + OFF_AH + off) = packh2(v0, v1);
            }
        }
    __syncthreads();

    // ---- phase-2: single-term GEMM, B-fragments via pipelined LDG ----
    for (int nt = 0; nt < 4; nt++) {
        float acc[2][7][4];
#pragma unroll
        for (int i = 0; i < 2; i++)
#pragma unroll
            for (int t = 0; t < 7; t++)
#pragma unroll
                for (int c = 0; c < 4; c++) acc[i][t][c] = 0.f;

        const uint2* bbase = g_W2p + (size_t)(nt * 25 + wn) * 512 + lane;

        uint2 Bq[2][7];
#pragma unroll
        for (int t = 0; t < 7; t++)
            if (wn == 0 || t < 6) Bq[0][t] = bbase[t * 2048];

#pragma unroll
        for (int q = 0; q < 16; q++) {
            const int cur = q & 1, nxt = cur ^ 1;
            if (q < 15) {
#pragma unroll
                for (int t = 0; t < 7; t++)
                    if (wn == 0 || t < 6) Bq[nxt][t] = bbase[t * 2048 + (q + 1) * 32];
            }
            uint32_t aH[2][4];
#pragma unroll
            for (int i = 0; i < 2; i++) {
                int r = wm * 32 + i * 16 + (lane & 15);
                int g = 2 * q + (lane >> 4);
                ldsm4(aH[i], sb + OFF_AH + aoff(r, g));
            }
#pragma unroll
            for (int t = 0; t < 7; t++)
                if (t < 6 || wn == 0) {
                    const uint32_t* bp = (const uint32_t*)&Bq[cur][t];
                    mma16816(acc[0][t], aH[0], bp);
                    mma16816(acc[1][t], aH[1], bp);
                }
        }

        // ---- epilogue: stage ALL 128 rows, one spline pass ----
#pragma unroll
        for (int i = 0; i < 2; i++)
#pragma unroll
            for (int t = 0; t < 7; t++)
                if (t < 6 || wn == 0) {
                    int col = (wn + 4 * t) * 8 + 2 * (lane & 3);
                    int r0 = wm * 32 + i * 16 + (lane >> 2);
                    *(float2*)&stage[r0 * 200 + col] =
                        make_float2(acc[i][t][0], acc[i][t][1]);
                    *(float2*)&stage[(r0 + 8) * 200 + col] =
                        make_float2(acc[i][t][2], acc[i][t][3]);
                }
        __syncthreads();

        // spline: 128 rows x 8 channels, 2 channels per thread (same row)
        {
            const int rl = tid >> 2;            // 0..127
            const int grow = rbase + rl;
            const float* xrow = X + (size_t)grow * D_IN + 32;
            float ladsum = 0.f;
#pragma unroll
            for (int qq = 0; qq < 2; qq++) {
                const int lc = (tid & 3) + qq * 4;   // 0..7
                const int ch = nt * 8 + lc;
                const float* sp = &stage[rl * 200 + lc * 25];
                const float* bp = &b2s[ch * 25];
                float pr[25];
#pragma unroll
                for (int j = 0; j < 25; j++) pr[j] = sp[j] + bp[j];

                // widths
                float mw = pr[0];
#pragma unroll
                for (int j = 1; j < 8; j++) mw = fmaxf(mw, pr[j]);
                float ew[8], sw = 0.f;
#pragma unroll
                for (int j = 0; j < 8; j++) { ew[j] = __expf(pr[j] - mw); sw += ew[j]; }
                float invw = __fdividef(1.f, sw);
                float w[8];
#pragma unroll
                for (int j = 0; j < 8; j++) w[j] = MINW + (1.f - MINW * 8.f) * ew[j] * invw;
                float cw[9]; cw[0] = 0.f;
#pragma unroll
                for (int j = 0; j < 8; j++) cw[j + 1] = cw[j] + w[j];
                float itw = __fdividef(1.f, fmaxf(cw[8], EPSC));
#pragma unroll
                for (int j = 0; j < 9; j++) cw[j] *= itw;
#pragma unroll
                for (int j = 0; j < 8; j++) w[j] = cw[j + 1] - cw[j];

                // heights
                float mhh = pr[8];
#pragma unroll
                for (int j = 1; j < 8; j++) mhh = fmaxf(mhh, pr[8 + j]);
                float eh[8], sh = 0.f;
#pragma unroll
                for (int j = 0; j < 8; j++) { eh[j] = __expf(pr[8 + j] - mhh); sh += eh[j]; }
                float invh = __fdividef(1.f, sh);
                float hh[8];
#pragma unroll
                for (int j = 0; j < 8; j++) hh[j] = MINW + (1.f - MINW * 8.f) * eh[j] * invh;
                float chh[9]; chh[0] = 0.f;
#pragma unroll
                for (int j = 0; j < 8; j++) chh[j + 1] = chh[j] + hh[j];
                float ith = __fdividef(1.f, fmaxf(chh[8], EPSC));
#pragma unroll
                for (int j = 0; j < 9; j++) chh[j] *= ith;
#pragma unroll
                for (int j = 0; j < 8; j++) hh[j] = chh[j + 1] - chh[j];

                // derivatives (softplus)
                float d[9];
#pragma unroll
                for (int j = 0; j < 9; j++) {
                    float u = pr[16 + j];
                    d[j] = MIND + fmaxf(u, 0.f) + __logf(1.f + __expf(-fabsf(u)));
                }

                const float x = xrow[ch];
                const bool inside = (x >= -10.f) && (x <= 10.f);
                float xs = fminf(fmaxf((x + 10.f) * 0.05f, 0.f), 1.f);

                float xk = cw[0], wk = w[0], yk = chh[0], hk = hh[0], dk = d[0], dk1 = d[1];
#pragma unroll
                for (int i = 0; i < 8; i++) {
                    if (xs >= cw[i]) {
                        xk = cw[i]; wk = w[i]; yk = chh[i]; hk = hh[i];
                        dk = d[i]; dk1 = d[i + 1];
                    }
                }
                float t   = fminf(fmaxf(__fdividef(xs - xk, wk + EPSC), 0.f), 1.f);
                float a   = __fdividef(hk + EPSC, wk + EPSC);
                float omt = 1.f - t;
                float num = a * t * t + dk * t * omt;
                float den = a + (dk + dk1 - 2.f * a) * t * omt;
                float s   = __fdividef(num, den + EPSC);
                float y   = (yk + hk * s) * 20.f - 10.f;
                float dnum = a * a * (dk1 * t * t + 2.f * a * t * omt + dk * omt * omt);
                float dydx = __fdividef(dnum, den * den + EPSC);
                float ladv = __logf(fmaxf(dydx, 1e-12f));

                out[(size_t)grow * D_IN + 32 + ch] = inside ? y : x;
                ladsum += inside ? ladv : 0.f;
            }
            // reduce 4 lanes (8 channels) per row
            ladsum += __shfl_xor_sync(0xffffffffu, ladsum, 1);
            ladsum += __shfl_xor_sync(0xffffffffu, ladsum, 2);
            if ((lane & 3) == 0) lad[rl] += ladsum;
        }
        __syncthreads();
    }

    if (tid < 128) out[(size_t)B * D_IN + rbase + tid] = lad[tid];
}

// ---------------------------------------------------------------------------
extern "C" void kernel_launch(void* const* d_in, const int* in_sizes, int n_in,
                              void* d_out, int out_size)
{
    const float* X  = (const float*)d_in[0];
    const float* W1 = (const float*)d_in[1];
    const float* b1 = (const float*)d_in[2];
    const float* W2 = (const float*)d_in[3];
    const float* b2 = (const float*)d_in[4];
    float* out = (float*)d_out;

    const int B = in_sizes[0] / D_IN;

    cudaFuncSetAttribute(kmain, cudaFuncAttributeMaxDynamicSharedMemorySize, SMEM_TOT);

    kprepW1<<<HID, 32>>>(W1);
    kprepW2<<<1600, 32>>>(W2);
    kmain<<<B / 128, 512, SMEM_TOT>>>(X, b1, b2, out, B);
}